// round 14
// baseline (speedup 1.0000x reference)
#include <cuda_runtime.h>
#include <cstdint>
#include <math.h>

// ---------------- problem constants ----------------
#define QLEN    1024
#define BATCH   4
#define DMODEL  1024
#define NHEAD   16
#define HDIM    64
#define MEMLEN  512
#define KLENC   1536
#define MLPD    4096
#define ATT_SCALE 0.125f
#define NROWS   4096
#define KROWS   6144

// ---------------- scratch ----------------
__device__ __align__(16) float g_cat[(size_t)KROWS * DMODEL];
__device__ __align__(16) float g_qkv[(size_t)KROWS * 3 * DMODEL];
__device__ __align__(16) float g_rh [(size_t)KLENC * DMODEL];
__device__ __align__(16) float g_S  [(size_t)64 * QLEN * KLENC];
__device__ __align__(16) float g_BD [(size_t)64 * QLEN * KLENC];
__device__ __align__(16) float g_Qu [(size_t)64 * QLEN * HDIM];
__device__ __align__(16) float g_Qv [(size_t)64 * QLEN * HDIM];
__device__ __align__(16) float g_rsum[(size_t)64 * QLEN];
__device__ __align__(16) float g_ctx[(size_t)NROWS * DMODEL];
__device__ __align__(16) float g_y  [(size_t)NROWS * DMODEL];
__device__ __align__(16) float g_x  [(size_t)NROWS * DMODEL];
__device__ __align__(16) float g_h  [(size_t)NROWS * MLPD];
__device__ __align__(16) float g_y2 [(size_t)NROWS * DMODEL];

// ---------------- helpers ----------------
__device__ __forceinline__ uint32_t smem_u32(const void* p) {
    uint32_t a;
    asm("{ .reg .u64 t; cvta.to.shared.u64 t, %1; cvt.u32.u64 %0, t; }" : "=r"(a) : "l"(p));
    return a;
}
__device__ __forceinline__ uint32_t tf32u(float x) {
    uint32_t u;
    asm("cvt.rna.tf32.f32 %0, %1;" : "=r"(u) : "f"(x));
    return u;
}
__device__ __forceinline__ void cpa16(uint32_t s, const void* g) {
    asm volatile("cp.async.cg.shared.global [%0], [%1], 16;" :: "r"(s), "l"(g));
}
__device__ __forceinline__ void cpcommit() {
    asm volatile("cp.async.commit_group;" ::: "memory");
}
__device__ __forceinline__ void mma_tf32(float* c, const uint32_t* a, const uint32_t* b)
{
    asm volatile(
        "mma.sync.aligned.m16n8k8.row.col.f32.tf32.tf32.f32 "
        "{%0,%1,%2,%3}, {%4,%5,%6,%7}, {%8,%9}, {%0,%1,%2,%3};"
        : "+f"(c[0]), "+f"(c[1]), "+f"(c[2]), "+f"(c[3])
        : "r"(a[0]), "r"(a[1]), "r"(a[2]), "r"(a[3]), "r"(b[0]), "r"(b[1]));
}

// K-chunk = 16 everywhere; dense GEMMs use R10's proven 3-stage / 2-CTA config.
#define SMP 20
#define BPN 136

// ============ mm_nn: C[M,N] = A[M,K] @ B[K,N], B row-major [K,N] ============
#define STG_NN (128 * SMP + 16 * BPN)
#define NN_SMEM (3 * STG_NN * 4)

__global__ __launch_bounds__(256, 2)
void mm_nn(const float* __restrict__ A, const float* __restrict__ B, float* __restrict__ C,
           int M, int N, int K, int lda, int ldb, int ldc,
           const float* __restrict__ bias, int relu)
{
    extern __shared__ float sm_[];
    uint32_t sb = smem_u32(sm_);
    int t = threadIdx.x, wid = t >> 5, lane = t & 31, g = lane >> 2, q = lane & 3;
    int row0 = blockIdx.y * 128, col0 = blockIdx.x * 128;
    int wm = (wid >> 2) * 64, wn = (wid & 3) * 32;

    int lrow = t >> 1, lkc = (t & 1) * 8;
    int krow = t >> 4, ncol = (t & 15) * 8;
    const float* Ag = A + (size_t)(row0 + lrow) * lda + lkc;
    const float* Bg = B + (size_t)krow * ldb + col0 + ncol;
    uint32_t as_s = sb + (uint32_t)((lrow * SMP + lkc) * 4);
    uint32_t bs_s = sb + (uint32_t)((128 * SMP + krow * BPN + ncol) * 4);

    float acc[4][4][4];
    #pragma unroll
    for (int i = 0; i < 4; i++)
        #pragma unroll
        for (int j = 0; j < 4; j++)
            #pragma unroll
            for (int v = 0; v < 4; v++) acc[i][j][v] = 0.f;

    int NC = K >> 4;
    auto issue = [&](int c) {
        uint32_t off = (uint32_t)(c % 3) * STG_NN * 4;
        const float* ag = Ag + c * 16;
        const float* bg = Bg + (size_t)c * 16 * ldb;
        cpa16(as_s + off, ag);       cpa16(as_s + off + 16, ag + 4);
        cpa16(bs_s + off, bg);       cpa16(bs_s + off + 16, bg + 4);
        cpcommit();
    };
    issue(0);
    if (NC > 1) issue(1);

    for (int c = 0; c < NC; c++) {
        if (c + 1 < NC) asm volatile("cp.async.wait_group 1;" ::: "memory");
        else            asm volatile("cp.async.wait_group 0;" ::: "memory");
        __syncthreads();
        if (c + 2 < NC) issue(c + 2);

        const float* As = sm_ + (c % 3) * STG_NN;
        const float* Bs = As + 128 * SMP;
        #pragma unroll
        for (int ks = 0; ks < 16; ks += 8) {
            uint32_t af[4][4], bf[4][2];
            #pragma unroll
            for (int mt = 0; mt < 4; mt++) {
                int r = wm + mt * 16 + g;
                af[mt][0] = tf32u(As[r * SMP + ks + q]);
                af[mt][1] = tf32u(As[(r + 8) * SMP + ks + q]);
                af[mt][2] = tf32u(As[r * SMP + ks + q + 4]);
                af[mt][3] = tf32u(As[(r + 8) * SMP + ks + q + 4]);
            }
            #pragma unroll
            for (int nt = 0; nt < 4; nt++) {
                int n = wn + nt * 8 + g;
                bf[nt][0] = tf32u(Bs[(ks + q) * BPN + n]);
                bf[nt][1] = tf32u(Bs[(ks + q + 4) * BPN + n]);
            }
            #pragma unroll
            for (int mt = 0; mt < 4; mt++)
                #pragma unroll
                for (int nt = 0; nt < 4; nt++)
                    mma_tf32(acc[mt][nt], af[mt], bf[nt]);
        }
    }

    #pragma unroll
    for (int mt = 0; mt < 4; mt++) {
        int row = row0 + wm + mt * 16 + g;
        #pragma unroll
        for (int nt = 0; nt < 4; nt++) {
            int col = col0 + wn + nt * 8 + q * 2;
            float b0 = bias ? bias[col] : 0.f;
            float b1 = bias ? bias[col + 1] : 0.f;
            float o0 = acc[mt][nt][0] + b0, o1 = acc[mt][nt][1] + b1;
            float o2 = acc[mt][nt][2] + b0, o3 = acc[mt][nt][3] + b1;
            if (relu) {
                o0 = fmaxf(o0, 0.f); o1 = fmaxf(o1, 0.f);
                o2 = fmaxf(o2, 0.f); o3 = fmaxf(o3, 0.f);
            }
            *(float2*)&C[(size_t)row * ldc + col]       = make_float2(o0, o1);
            *(float2*)&C[(size_t)(row + 8) * ldc + col] = make_float2(o2, o3);
        }
    }
}

// ============ mm_nt64: C = A @ B^T, 128x64 tile, 3 CTAs/SM; batched over z ============
// Warp grid 4(m) x 2(n); warp tile 32x32 -> 32 acc regs.
#define STG_NT64 (128 * SMP + 64 * SMP)          // 3840 floats/stage
#define NT64_SMEM (3 * STG_NT64 * 4)             // 46080 B

__global__ __launch_bounds__(256, 3)
void mm_nt64(const float* __restrict__ A, const float* __restrict__ B, float* __restrict__ C,
             int lda, int ldb, int ldc,
             long sAz, long sBh, long sCz, int skipSum)
{
    int row0 = blockIdx.y * 128, col0 = blockIdx.x * 64;
    if (skipSum && row0 + col0 < skipSum) return;
    extern __shared__ float sm_[];
    uint32_t sb = smem_u32(sm_);
    int t = threadIdx.x, wid = t >> 5, lane = t & 31, g = lane >> 2, q = lane & 3;
    int z = blockIdx.z;
    const float* Az = A + (size_t)z * sAz;
    const float* Bz = B + (size_t)(z & 15) * sBh;
    float* Cz = C + (size_t)z * sCz;
    int wm = (wid >> 1) * 32, wn = (wid & 1) * 32;

    int lrow = t >> 1, lkc = (t & 1) * 8;
    const float* Ag = Az + (size_t)(row0 + lrow) * lda + lkc;
    const float* Bg = Bz + (size_t)(col0 + (lrow & 63)) * ldb + lkc;   // t<128 loads B
    uint32_t as_s = sb + (uint32_t)((lrow * SMP + lkc) * 4);
    uint32_t bs_s = sb + (uint32_t)((128 * SMP + (lrow & 63) * SMP + lkc) * 4);

    float acc[2][4][4];
    #pragma unroll
    for (int i = 0; i < 2; i++)
        #pragma unroll
        for (int j = 0; j < 4; j++)
            #pragma unroll
            for (int v = 0; v < 4; v++) acc[i][j][v] = 0.f;

    auto issue = [&](int c) {
        uint32_t off = (uint32_t)(c % 3) * STG_NT64 * 4;
        const float* ag = Ag + c * 16;
        cpa16(as_s + off, ag); cpa16(as_s + off + 16, ag + 4);
        if (t < 128) {
            const float* bg = Bg + c * 16;
            cpa16(bs_s + off, bg); cpa16(bs_s + off + 16, bg + 4);
        }
        cpcommit();
    };
    issue(0); issue(1);

    #pragma unroll
    for (int c = 0; c < 4; c++) {                 // K = 64
        if (c + 1 < 4) asm volatile("cp.async.wait_group 1;" ::: "memory");
        else           asm volatile("cp.async.wait_group 0;" ::: "memory");
        __syncthreads();
        if (c + 2 < 4) issue(c + 2);

        const float* As = sm_ + (c % 3) * STG_NT64;
        const float* Bs = As + 128 * SMP;
        #pragma unroll
        for (int ks = 0; ks < 16; ks += 8) {
            uint32_t af[2][4], bf[4][2];
            #pragma unroll
            for (int mt = 0; mt < 2; mt++) {
                int r = wm + mt * 16 + g;
                af[mt][0] = tf32u(As[r * SMP + ks + q]);
                af[mt][1] = tf32u(As[(r + 8) * SMP + ks + q]);
                af[mt][2] = tf32u(As[r * SMP + ks + q + 4]);
                af[mt][3] = tf32u(As[(r + 8) * SMP + ks + q + 4]);
            }
            #pragma unroll
            for (int nt = 0; nt < 4; nt++) {
                int rn = wn + nt * 8 + g;
                bf[nt][0] = tf32u(Bs[rn * SMP + ks + q]);
                bf[nt][1] = tf32u(Bs[rn * SMP + ks + q + 4]);
            }
            #pragma unroll
            for (int mt = 0; mt < 2; mt++)
                #pragma unroll
                for (int nt = 0; nt < 4; nt++)
                    mma_tf32(acc[mt][nt], af[mt], bf[nt]);
        }
    }

    #pragma unroll
    for (int mt = 0; mt < 2; mt++) {
        int row = row0 + wm + mt * 16 + g;
        #pragma unroll
        for (int nt = 0; nt < 4; nt++) {
            int col = col0 + wn + nt * 8 + q * 2;
            *(float2*)&Cz[(size_t)row * ldc + col] =
                make_float2(acc[mt][nt][0], acc[mt][nt][1]);
            *(float2*)&Cz[(size_t)(row + 8) * ldc + col] =
                make_float2(acc[mt][nt][2], acc[mt][nt][3]);
        }
    }
}

// ============ ac_fused64: AC GEMM (128x64 tile) + BD-shift + mask + exp + rowsum ============
__global__ __launch_bounds__(256, 3)
void ac_fused64(const float* __restrict__ Qu, const float* __restrict__ qkv,
                const float* __restrict__ BD, float* __restrict__ S,
                float* __restrict__ rsum)
{
    int i0 = blockIdx.y * 128, j0 = blockIdx.x * 64;
    if (j0 > i0 + 639) return;
    extern __shared__ float sm_[];
    uint32_t sb = smem_u32(sm_);
    int t = threadIdx.x, wid = t >> 5, lane = t & 31, g = lane >> 2, q = lane & 3;
    int z = blockIdx.z, bb = z >> 4, hh = z & 15;
    int wm = (wid >> 1) * 32, wn = (wid & 1) * 32;

    int lrow = t >> 1, lkc = (t & 1) * 8;
    const float* Ag = Qu + (size_t)z * QLEN * HDIM + (size_t)(i0 + lrow) * HDIM + lkc;
    const float* Bg = qkv + ((size_t)(j0 + (lrow & 63)) * 4 + bb) * 3072 + 1024 + hh * 64 + lkc;
    uint32_t as_s = sb + (uint32_t)((lrow * SMP + lkc) * 4);
    uint32_t bs_s = sb + (uint32_t)((128 * SMP + (lrow & 63) * SMP + lkc) * 4);

    float acc[2][4][4];
    #pragma unroll
    for (int i = 0; i < 2; i++)
        #pragma unroll
        for (int j = 0; j < 4; j++)
            #pragma unroll
            for (int v = 0; v < 4; v++) acc[i][j][v] = 0.f;

    auto issue = [&](int c) {
        uint32_t off = (uint32_t)(c % 3) * STG_NT64 * 4;
        const float* ag = Ag + c * 16;
        cpa16(as_s + off, ag); cpa16(as_s + off + 16, ag + 4);
        if (t < 128) {
            const float* bg = Bg + c * 16;
            cpa16(bs_s + off, bg); cpa16(bs_s + off + 16, bg + 4);
        }
        cpcommit();
    };
    issue(0); issue(1);

    #pragma unroll
    for (int c = 0; c < 4; c++) {                 // K = 64
        if (c + 1 < 4) asm volatile("cp.async.wait_group 1;" ::: "memory");
        else           asm volatile("cp.async.wait_group 0;" ::: "memory");
        __syncthreads();
        if (c + 2 < 4) issue(c + 2);

        const float* As = sm_ + (c % 3) * STG_NT64;
        const float* Bs = As + 128 * SMP;
        #pragma unroll
        for (int ks = 0; ks < 16; ks += 8) {
            uint32_t af[2][4], bf[4][2];
            #pragma unroll
            for (int mt = 0; mt < 2; mt++) {
                int r = wm + mt * 16 + g;
                af[mt][0] = tf32u(As[r * SMP + ks + q]);
                af[mt][1] = tf32u(As[(r + 8) * SMP + ks + q]);
                af[mt][2] = tf32u(As[r * SMP + ks + q + 4]);
                af[mt][3] = tf32u(As[(r + 8) * SMP + ks + q + 4]);
            }
            #pragma unroll
            for (int nt = 0; nt < 4; nt++) {
                int rn = wn + nt * 8 + g;
                bf[nt][0] = tf32u(Bs[rn * SMP + ks + q]);
                bf[nt][1] = tf32u(Bs[rn * SMP + ks + q + 4]);
            }
            #pragma unroll
            for (int mt = 0; mt < 2; mt++)
                #pragma unroll
                for (int nt = 0; nt < 4; nt++)
                    mma_tf32(acc[mt][nt], af[mt], bf[nt]);
        }
    }

    const float* BDz = BD + (size_t)z * QLEN * KLENC;
    float* Sz = S + (size_t)z * QLEN * KLENC;
    float* rz = rsum + (size_t)z * QLEN;
    #pragma unroll
    for (int mt = 0; mt < 2; mt++) {
        int r0i = i0 + wm + mt * 16 + g;
        int r1i = r0i + 8;
        float s0 = 0.f, s1 = 0.f;
        const float* bd0 = BDz + (size_t)r0i * KLENC + (1023 - r0i);
        const float* bd1 = BDz + (size_t)r1i * KLENC + (1023 - r1i);
        #pragma unroll
        for (int nt = 0; nt < 4; nt++) {
            int col = j0 + wn + nt * 8 + q * 2;
            int v00 = (col     <= r0i + 512);
            int v01 = (col + 1 <= r0i + 512);
            int v10 = (col     <= r1i + 512);
            int v11 = (col + 1 <= r1i + 512);
            float p00 = v00 ? __expf((acc[mt][nt][0] + bd0[col])     * ATT_SCALE) : 0.f;
            float p01 = v01 ? __expf((acc[mt][nt][1] + bd0[col + 1]) * ATT_SCALE) : 0.f;
            float p10 = v10 ? __expf((acc[mt][nt][2] + bd1[col])     * ATT_SCALE) : 0.f;
            float p11 = v11 ? __expf((acc[mt][nt][3] + bd1[col + 1]) * ATT_SCALE) : 0.f;
            s0 += p00 + p01;
            s1 += p10 + p11;
            *(float2*)&Sz[(size_t)r0i * KLENC + col] = make_float2(p00, p01);
            *(float2*)&Sz[(size_t)r1i * KLENC + col] = make_float2(p10, p11);
        }
        s0 += __shfl_xor_sync(0xffffffffu, s0, 1);
        s0 += __shfl_xor_sync(0xffffffffu, s0, 2);
        s1 += __shfl_xor_sync(0xffffffffu, s1, 1);
        s1 += __shfl_xor_sync(0xffffffffu, s1, 2);
        if (q == 0) {
            atomicAdd(&rz[r0i], s0);
            atomicAdd(&rz[r1i], s1);
        }
    }
}

// ============ PV: ctx = (P @ V) / rsum (unchanged from R10) ============
#define VPV 72
#define STG_PV (128 * SMP + 16 * VPV)
#define PV_SMEM (3 * STG_PV * 4)

__global__ __launch_bounds__(256, 2)
void pv_mma(const float* __restrict__ S, const float* __restrict__ qkv,
            const float* __restrict__ rsum, float* __restrict__ ctx)
{
    extern __shared__ float sm_[];
    uint32_t sb = smem_u32(sm_);
    int t = threadIdx.x, wid = t >> 5, lane = t & 31, g = lane >> 2, q = lane & 3;
    int i0 = blockIdx.x * 128;
    int z = blockIdx.y, bb = z >> 4, hh = z & 15;
    int wm = (wid >> 1) * 32, wn = (wid & 1) * 32;

    const float* Ag = S + ((size_t)z * QLEN + i0 + (t >> 1)) * KLENC + (t & 1) * 8;
    uint32_t as_s = sb + (uint32_t)(((t >> 1) * SMP + (t & 1) * 8) * 4);
    int vrow = (t & 127) >> 3, vcol = (t & 7) * 8;
    uint32_t vs_s = sb + (uint32_t)((128 * SMP + vrow * VPV + vcol) * 4);

    float acc[2][4][4];
    #pragma unroll
    for (int i = 0; i < 2; i++)
        #pragma unroll
        for (int j = 0; j < 4; j++)
            #pragma unroll
            for (int v = 0; v < 4; v++) acc[i][j][v] = 0.f;

    int jlim = i0 + 640; if (jlim > KLENC) jlim = KLENC;
    int NC = jlim >> 4;

    auto issue = [&](int c) {
        uint32_t off = (uint32_t)(c % 3) * STG_PV * 4;
        const float* ag = Ag + c * 16;
        cpa16(as_s + off, ag); cpa16(as_s + off + 16, ag + 4);
        if (t < 128) {
            const float* vg = qkv + ((size_t)((c * 16 + vrow) * 4 + bb)) * 3072 + 2048 + hh * 64 + vcol;
            cpa16(vs_s + off, vg); cpa16(vs_s + off + 16, vg + 4);
        }
        cpcommit();
    };
    issue(0);
    if (NC > 1) issue(1);

    for (int c = 0; c < NC; c++) {
        if (c + 1 < NC) asm volatile("cp.async.wait_group 1;" ::: "memory");
        else            asm volatile("cp.async.wait_group 0;" ::: "memory");
        __syncthreads();
        if (c + 2 < NC) issue(c + 2);

        const float* As = sm_ + (c % 3) * STG_PV;
        const float* Vs = As + 128 * SMP;
        #pragma unroll
        for (int ks = 0; ks < 16; ks += 8) {
            uint32_t af[2][4], bf[4][2];
            #pragma unroll
            for (int mt = 0; mt < 2; mt++) {
                int r = wm + mt * 16 + g;
                af[mt][0] = tf32u(As[r * SMP + ks + q]);
                af[mt][1] = tf32u(As[(r + 8) * SMP + ks + q]);
                af[mt][2] = tf32u(As[r * SMP + ks + q + 4]);
                af[mt][3] = tf32u(As[(r + 8) * SMP + ks + q + 4]);
            }
            #pragma unroll
            for (int nt = 0; nt < 4; nt++) {
                int n = wn + nt * 8 + g;
                bf[nt][0] = tf32u(Vs[(ks + q) * VPV + n]);
                bf[nt][1] = tf32u(Vs[(ks + q + 4) * VPV + n]);
            }
            #pragma unroll
            for (int mt = 0; mt < 2; mt++)
                #pragma unroll
                for (int nt = 0; nt < 4; nt++)
                    mma_tf32(acc[mt][nt], af[mt], bf[nt]);
        }
    }

    const float* rz = rsum + (size_t)z * QLEN;
    #pragma unroll
    for (int mt = 0; mt < 2; mt++) {
        int m = i0 + wm + mt * 16 + g;
        float inv0 = 1.f / rz[m];
        float inv1 = 1.f / rz[m + 8];
        #pragma unroll
        for (int nt = 0; nt < 4; nt++) {
            int d = wn + nt * 8 + q * 2;
            size_t o0 = ((size_t)m * 4 + bb) * 1024 + hh * 64 + d;
            size_t o1 = ((size_t)(m + 8) * 4 + bb) * 1024 + hh * 64 + d;
            *(float2*)&ctx[o0] = make_float2(acc[mt][nt][0] * inv0, acc[mt][nt][1] * inv0);
            *(float2*)&ctx[o1] = make_float2(acc[mt][nt][2] * inv1, acc[mt][nt][3] * inv1);
        }
    }
}

// ---------------- Qu/Qv prep ----------------
__global__ void quv_prep(const float* __restrict__ qkv, const float* __restrict__ u,
                         const float* __restrict__ v, float* __restrict__ Qu,
                         float* __restrict__ Qv)
{
    size_t idx = (size_t)blockIdx.x * 256 + threadIdx.x;
    int d = idx & 63;
    size_t row = idx >> 6;
    int i = row & 1023;
    int z = row >> 10, bb = z >> 4, hh = z & 15;
    float qv = qkv[((size_t)((MEMLEN + i) * 4 + bb)) * 3072 + hh * 64 + d];
    Qu[idx] = qv + u[hh * 64 + d];
    Qv[idx] = qv + v[hh * 64 + d];
}

// ---------------- layernorm ----------------
__device__ __forceinline__ float block_sum256(float v, float* red)
{
    #pragma unroll
    for (int o = 16; o; o >>= 1) v += __shfl_xor_sync(0xffffffffu, v, o);
    if ((threadIdx.x & 31) == 0) red[threadIdx.x >> 5] = v;
    __syncthreads();
    float s = 0.f;
    #pragma unroll
    for (int w = 0; w < 8; w++) s += red[w];
    __syncthreads();
    return s;
}

__global__ void ln_kernel(const float* __restrict__ A, const float* __restrict__ Bv,
                          const float* __restrict__ g, const float* __restrict__ be,
                          float* __restrict__ out)
{
    int row = blockIdx.x;
    int t = threadIdx.x;
    __shared__ float red[8];
    size_t base = (size_t)row * DMODEL;

    float x[4];
    float s = 0.f;
    #pragma unroll
    for (int r = 0; r < 4; r++) {
        int c = t + r * 256;
        x[r] = A[base + c] + Bv[base + c];
        s += x[r];
    }
    float mean = block_sum256(s, red) * (1.f / DMODEL);

    float q = 0.f;
    #pragma unroll
    for (int r = 0; r < 4; r++) {
        float d = x[r] - mean;
        q += d * d;
    }
    float var = block_sum256(q, red) * (1.f / DMODEL);
    float rstd = rsqrtf(var + 1e-5f);

    #pragma unroll
    for (int r = 0; r < 4; r++) {
        int c = t + r * 256;
        out[base + c] = (x[r] - mean) * rstd * g[c] + be[c];
    }
}

// ---------------- host orchestration ----------------
extern "C" void kernel_launch(void* const* d_in, const int* in_sizes, int n_in,
                              void* d_out, int out_size)
{
    (void)in_sizes; (void)out_size;
    int off = (n_in >= 17) ? 0 : -1;
    const float* inp   = (const float*)d_in[0];
    const float* r     = (const float*)d_in[1];
    const float* u     = (const float*)d_in[2];
    const float* v     = (const float*)d_in[3];
    const float* mem   = (const float*)d_in[4];
    const float* W_qkv = (const float*)d_in[6 + off];
    const float* W_r   = (const float*)d_in[7 + off];
    const float* W_o   = (const float*)d_in[8 + off];
    const float* ln1g  = (const float*)d_in[9 + off];
    const float* ln1b  = (const float*)d_in[10 + off];
    const float* ln2g  = (const float*)d_in[11 + off];
    const float* ln2b  = (const float*)d_in[12 + off];
    const float* W1    = (const float*)d_in[13 + off];
    const float* b1    = (const float*)d_in[14 + off];
    const float* W2    = (const float*)d_in[15 + off];
    const float* b2    = (const float*)d_in[16 + off];
    float* out = (float*)d_out;

    float *cat_p, *qkv_p, *rh_p, *S_p, *BD_p, *Qu_p, *Qv_p, *rs_p, *ctx_p, *y_p, *x_p, *h_p, *y2_p;
    cudaGetSymbolAddress((void**)&cat_p, g_cat);
    cudaGetSymbolAddress((void**)&qkv_p, g_qkv);
    cudaGetSymbolAddress((void**)&rh_p,  g_rh);
    cudaGetSymbolAddress((void**)&S_p,   g_S);
    cudaGetSymbolAddress((void**)&BD_p,  g_BD);
    cudaGetSymbolAddress((void**)&Qu_p,  g_Qu);
    cudaGetSymbolAddress((void**)&Qv_p,  g_Qv);
    cudaGetSymbolAddress((void**)&rs_p,  g_rsum);
    cudaGetSymbolAddress((void**)&ctx_p, g_ctx);
    cudaGetSymbolAddress((void**)&y_p,   g_y);
    cudaGetSymbolAddress((void**)&x_p,   g_x);
    cudaGetSymbolAddress((void**)&h_p,   g_h);
    cudaGetSymbolAddress((void**)&y2_p,  g_y2);

    cudaFuncSetAttribute(mm_nn,      cudaFuncAttributeMaxDynamicSharedMemorySize, NN_SMEM);
    cudaFuncSetAttribute(mm_nt64,    cudaFuncAttributeMaxDynamicSharedMemorySize, NT64_SMEM);
    cudaFuncSetAttribute(ac_fused64, cudaFuncAttributeMaxDynamicSharedMemorySize, NT64_SMEM);
    cudaFuncSetAttribute(pv_mma,     cudaFuncAttributeMaxDynamicSharedMemorySize, PV_SMEM);

    // cat = [mem; inputs]
    cudaMemcpyAsync(cat_p, mem, (size_t)MEMLEN * BATCH * DMODEL * sizeof(float),
                    cudaMemcpyDeviceToDevice);
    cudaMemcpyAsync(cat_p + (size_t)MEMLEN * BATCH * DMODEL, inp,
                    (size_t)QLEN * BATCH * DMODEL * sizeof(float),
                    cudaMemcpyDeviceToDevice);
    cudaMemsetAsync(rs_p, 0, (size_t)64 * QLEN * sizeof(float));

    dim3 blk(256);
    // qkv = cat @ W_qkv
    mm_nn<<<dim3(3072/128, 6144/128), blk, NN_SMEM>>>(
        cat_p, W_qkv, qkv_p, 6144, 3072, 1024, 1024, 3072, 3072, nullptr, 0);
    // r_h = r @ W_r
    mm_nn<<<dim3(1024/128, 1536/128), blk, NN_SMEM>>>(
        r, W_r, rh_p, 1536, 1024, 1024, 1024, 1024, 1024, nullptr, 0);
    // Qu/Qv prep
    quv_prep<<<(64 * QLEN * HDIM) / 256, 256>>>(qkv_p, u, v, Qu_p, Qv_p);
    // BD[z] = Qv @ rh[:, h*64:h*64+64]^T; dead iff i0+col0 < 833 (64-wide tiles)
    mm_nt64<<<dim3(KLENC/64, QLEN/128, 64), blk, NT64_SMEM>>>(
        Qv_p, rh_p, BD_p, 64, 1024, 1536,
        (long)1024*64, 64, (long)1024*1536, 833);
    // P = exp(mask(AC + shift(BD)) * scale), rowsum -> rsum
    ac_fused64<<<dim3(KLENC/64, QLEN/128, 64), blk, NT64_SMEM>>>(
        Qu_p, qkv_p, BD_p, S_p, rs_p);
    // ctx = (P @ V) / rsum
    pv_mma<<<dim3(QLEN/128, 64), blk, PV_SMEM>>>(S_p, qkv_p, rs_p, ctx_p);
    // y = ctx @ W_o
    mm_nn<<<dim3(1024/128, 4096/128), blk, NN_SMEM>>>(
        ctx_p, W_o, y_p, 4096, 1024, 1024, 1024, 1024, 1024, nullptr, 0);
    ln_kernel<<<NROWS, 256>>>(inp, y_p, ln1g, ln1b, x_p);
    // h = relu(x @ W1 + b1)
    mm_nn<<<dim3(4096/128, 4096/128), blk, NN_SMEM>>>(
        x_p, W1, h_p, 4096, 4096, 1024, 1024, 4096, 4096, b1, 1);
    // y2 = h @ W2 + b2
    mm_nn<<<dim3(1024/128, 4096/128), blk, NN_SMEM>>>(
        h_p, W2, y2_p, 4096, 1024, 4096, 4096, 1024, 1024, b2, 0);
    ln_kernel<<<NROWS, 256>>>(x_p, y2_p, ln2g, ln2b, out);
}

// round 15
// speedup vs baseline: 1.7531x; 1.7531x over previous
#include <cuda_runtime.h>
#include <cuda_bf16.h>
#include <cstdint>
#include <math.h>

// ---------------- problem constants ----------------
#define QLEN    1024
#define BATCH   4
#define DMODEL  1024
#define NHEAD   16
#define HDIM    64
#define MEMLEN  512
#define KLENC   1536
#define MLPD    4096
#define ATT_SCALE 0.125f
#define NROWS   4096
#define KROWS   6144

// ---------------- scratch ----------------
__device__ __align__(16) float g_cat[(size_t)KROWS * DMODEL];
__device__ __align__(16) float g_qkv[(size_t)KROWS * 3 * DMODEL];
__device__ __align__(16) float g_rh [(size_t)KLENC * DMODEL];
__device__ __align__(16) __nv_bfloat16 g_S [(size_t)64 * QLEN * KLENC];   // probs, bf16
__device__ __align__(16) __nv_bfloat16 g_BD[(size_t)64 * QLEN * KLENC];   // BD, bf16
__device__ __align__(16) float g_Qu [(size_t)64 * QLEN * HDIM];
__device__ __align__(16) float g_Qv [(size_t)64 * QLEN * HDIM];
__device__ __align__(16) float g_rsum[(size_t)64 * QLEN];
__device__ __align__(16) float g_ctx[(size_t)NROWS * DMODEL];
__device__ __align__(16) float g_y  [(size_t)NROWS * DMODEL];
__device__ __align__(16) float g_x  [(size_t)NROWS * DMODEL];
__device__ __align__(16) float g_h  [(size_t)NROWS * MLPD];
__device__ __align__(16) float g_y2 [(size_t)NROWS * DMODEL];

// ---------------- helpers ----------------
__device__ __forceinline__ uint32_t smem_u32(const void* p) {
    uint32_t a;
    asm("{ .reg .u64 t; cvta.to.shared.u64 t, %1; cvt.u32.u64 %0, t; }" : "=r"(a) : "l"(p));
    return a;
}
__device__ __forceinline__ uint32_t tf32u(float x) {
    uint32_t u;
    asm("cvt.rna.tf32.f32 %0, %1;" : "=r"(u) : "f"(x));
    return u;
}
__device__ __forceinline__ void cpa16(uint32_t s, const void* g) {
    asm volatile("cp.async.cg.shared.global [%0], [%1], 16;" :: "r"(s), "l"(g));
}
__device__ __forceinline__ void cpcommit() {
    asm volatile("cp.async.commit_group;" ::: "memory");
}
__device__ __forceinline__ void mma_tf32(float* c, const uint32_t* a, const uint32_t* b)
{
    asm volatile(
        "mma.sync.aligned.m16n8k8.row.col.f32.tf32.tf32.f32 "
        "{%0,%1,%2,%3}, {%4,%5,%6,%7}, {%8,%9}, {%0,%1,%2,%3};"
        : "+f"(c[0]), "+f"(c[1]), "+f"(c[2]), "+f"(c[3])
        : "r"(a[0]), "r"(a[1]), "r"(a[2]), "r"(a[3]), "r"(b[0]), "r"(b[1]));
}
// pack two floats -> bf16x2 (stored as uint32)
__device__ __forceinline__ uint32_t bf2pack(float lo, float hi) {
    __nv_bfloat162 p = __floats2bfloat162_rn(lo, hi);
    return *(uint32_t*)&p;
}

// K-chunk = 16, 3-stage ring (R10 measured-best config).
#define SMP 20
#define BPN 136

// ============ mm_nn: C[M,N] = A[M,K] @ B[K,N], B row-major [K,N] ============
#define STG_NN (128 * SMP + 16 * BPN)
#define NN_SMEM (3 * STG_NN * 4)

__global__ __launch_bounds__(256, 2)
void mm_nn(const float* __restrict__ A, const float* __restrict__ B, float* __restrict__ C,
           int M, int N, int K, int lda, int ldb, int ldc,
           const float* __restrict__ bias, int relu)
{
    extern __shared__ float sm_[];
    uint32_t sb = smem_u32(sm_);
    int t = threadIdx.x, wid = t >> 5, lane = t & 31, g = lane >> 2, q = lane & 3;
    int row0 = blockIdx.y * 128, col0 = blockIdx.x * 128;
    int wm = (wid >> 2) * 64, wn = (wid & 3) * 32;

    int lrow = t >> 1, lkc = (t & 1) * 8;
    int krow = t >> 4, ncol = (t & 15) * 8;
    const float* Ag = A + (size_t)(row0 + lrow) * lda + lkc;
    const float* Bg = B + (size_t)krow * ldb + col0 + ncol;
    uint32_t as_s = sb + (uint32_t)((lrow * SMP + lkc) * 4);
    uint32_t bs_s = sb + (uint32_t)((128 * SMP + krow * BPN + ncol) * 4);

    float acc[4][4][4];
    #pragma unroll
    for (int i = 0; i < 4; i++)
        #pragma unroll
        for (int j = 0; j < 4; j++)
            #pragma unroll
            for (int v = 0; v < 4; v++) acc[i][j][v] = 0.f;

    int NC = K >> 4;
    auto issue = [&](int c) {
        uint32_t off = (uint32_t)(c % 3) * STG_NN * 4;
        const float* ag = Ag + c * 16;
        const float* bg = Bg + (size_t)c * 16 * ldb;
        cpa16(as_s + off, ag);       cpa16(as_s + off + 16, ag + 4);
        cpa16(bs_s + off, bg);       cpa16(bs_s + off + 16, bg + 4);
        cpcommit();
    };
    issue(0);
    if (NC > 1) issue(1);

    for (int c = 0; c < NC; c++) {
        if (c + 1 < NC) asm volatile("cp.async.wait_group 1;" ::: "memory");
        else            asm volatile("cp.async.wait_group 0;" ::: "memory");
        __syncthreads();
        if (c + 2 < NC) issue(c + 2);

        const float* As = sm_ + (c % 3) * STG_NN;
        const float* Bs = As + 128 * SMP;
        #pragma unroll
        for (int ks = 0; ks < 16; ks += 8) {
            uint32_t af[4][4], bf[4][2];
            #pragma unroll
            for (int mt = 0; mt < 4; mt++) {
                int r = wm + mt * 16 + g;
                af[mt][0] = tf32u(As[r * SMP + ks + q]);
                af[mt][1] = tf32u(As[(r + 8) * SMP + ks + q]);
                af[mt][2] = tf32u(As[r * SMP + ks + q + 4]);
                af[mt][3] = tf32u(As[(r + 8) * SMP + ks + q + 4]);
            }
            #pragma unroll
            for (int nt = 0; nt < 4; nt++) {
                int n = wn + nt * 8 + g;
                bf[nt][0] = tf32u(Bs[(ks + q) * BPN + n]);
                bf[nt][1] = tf32u(Bs[(ks + q + 4) * BPN + n]);
            }
            #pragma unroll
            for (int mt = 0; mt < 4; mt++)
                #pragma unroll
                for (int nt = 0; nt < 4; nt++)
                    mma_tf32(acc[mt][nt], af[mt], bf[nt]);
        }
    }

    #pragma unroll
    for (int mt = 0; mt < 4; mt++) {
        int row = row0 + wm + mt * 16 + g;
        #pragma unroll
        for (int nt = 0; nt < 4; nt++) {
            int col = col0 + wn + nt * 8 + q * 2;
            float b0 = bias ? bias[col] : 0.f;
            float b1 = bias ? bias[col + 1] : 0.f;
            float o0 = acc[mt][nt][0] + b0, o1 = acc[mt][nt][1] + b1;
            float o2 = acc[mt][nt][2] + b0, o3 = acc[mt][nt][3] + b1;
            if (relu) {
                o0 = fmaxf(o0, 0.f); o1 = fmaxf(o1, 0.f);
                o2 = fmaxf(o2, 0.f); o3 = fmaxf(o3, 0.f);
            }
            *(float2*)&C[(size_t)row * ldc + col]       = make_float2(o0, o1);
            *(float2*)&C[(size_t)(row + 8) * ldc + col] = make_float2(o2, o3);
        }
    }
}

// ============ mm_nt_bf: C(bf16) = A @ B^T, batched over z; used for BD ============
#define STG_NT (2 * 128 * SMP)
#define NT_SMEM (3 * STG_NT * 4)

__global__ __launch_bounds__(256, 2)
void mm_nt_bf(const float* __restrict__ A, const float* __restrict__ B,
              __nv_bfloat16* __restrict__ C,
              int lda, int ldb, int ldc,
              long sAz, long sBh, long sCz, int skipSum, int NC)
{
    int row0 = blockIdx.y * 128, col0 = blockIdx.x * 128;
    if (skipSum && row0 + col0 < skipSum) return;
    extern __shared__ float sm_[];
    uint32_t sb = smem_u32(sm_);
    int t = threadIdx.x, wid = t >> 5, lane = t & 31, g = lane >> 2, q = lane & 3;
    int z = blockIdx.z;
    const float* Az = A + (size_t)z * sAz;
    const float* Bz = B + (size_t)(z & 15) * sBh;
    __nv_bfloat16* Cz = C + (size_t)z * sCz;
    int wm = (wid >> 2) * 64, wn = (wid & 3) * 32;

    int lrow = t >> 1, lkc = (t & 1) * 8;
    const float* Ag = Az + (size_t)(row0 + lrow) * lda + lkc;
    const float* Bg = Bz + (size_t)(col0 + lrow) * ldb + lkc;
    uint32_t as_s = sb + (uint32_t)((lrow * SMP + lkc) * 4);
    uint32_t bs_s = as_s + 128 * SMP * 4;

    float acc[4][4][4];
    #pragma unroll
    for (int i = 0; i < 4; i++)
        #pragma unroll
        for (int j = 0; j < 4; j++)
            #pragma unroll
            for (int v = 0; v < 4; v++) acc[i][j][v] = 0.f;

    auto issue = [&](int c) {
        uint32_t off = (uint32_t)(c % 3) * STG_NT * 4;
        const float* ag = Ag + c * 16;
        const float* bg = Bg + c * 16;
        cpa16(as_s + off, ag); cpa16(as_s + off + 16, ag + 4);
        cpa16(bs_s + off, bg); cpa16(bs_s + off + 16, bg + 4);
        cpcommit();
    };
    issue(0);
    if (NC > 1) issue(1);

    for (int c = 0; c < NC; c++) {
        if (c + 1 < NC) asm volatile("cp.async.wait_group 1;" ::: "memory");
        else            asm volatile("cp.async.wait_group 0;" ::: "memory");
        __syncthreads();
        if (c + 2 < NC) issue(c + 2);

        const float* As = sm_ + (c % 3) * STG_NT;
        const float* Bs = As + 128 * SMP;
        #pragma unroll
        for (int ks = 0; ks < 16; ks += 8) {
            uint32_t af[4][4], bf[4][2];
            #pragma unroll
            for (int mt = 0; mt < 4; mt++) {
                int r = wm + mt * 16 + g;
                af[mt][0] = tf32u(As[r * SMP + ks + q]);
                af[mt][1] = tf32u(As[(r + 8) * SMP + ks + q]);
                af[mt][2] = tf32u(As[r * SMP + ks + q + 4]);
                af[mt][3] = tf32u(As[(r + 8) * SMP + ks + q + 4]);
            }
            #pragma unroll
            for (int nt = 0; nt < 4; nt++) {
                int rn = wn + nt * 8 + g;
                bf[nt][0] = tf32u(Bs[rn * SMP + ks + q]);
                bf[nt][1] = tf32u(Bs[rn * SMP + ks + q + 4]);
            }
            #pragma unroll
            for (int mt = 0; mt < 4; mt++)
                #pragma unroll
                for (int nt = 0; nt < 4; nt++)
                    mma_tf32(acc[mt][nt], af[mt], bf[nt]);
        }
    }

    #pragma unroll
    for (int mt = 0; mt < 4; mt++) {
        int row = row0 + wm + mt * 16 + g;
        #pragma unroll
        for (int nt = 0; nt < 4; nt++) {
            int col = col0 + wn + nt * 8 + q * 2;
            *(uint32_t*)&Cz[(size_t)row * ldc + col] =
                bf2pack(acc[mt][nt][0], acc[mt][nt][1]);
            *(uint32_t*)&Cz[(size_t)(row + 8) * ldc + col] =
                bf2pack(acc[mt][nt][2], acc[mt][nt][3]);
        }
    }
}

// ============ AC GEMM + BD(bf16)-shift + mask + exp -> P(bf16) + rowsum ============
__global__ __launch_bounds__(256, 2)
void ac_fused(const float* __restrict__ Qu, const float* __restrict__ qkv,
              const __nv_bfloat16* __restrict__ BD, __nv_bfloat16* __restrict__ S,
              float* __restrict__ rsum)
{
    int i0 = blockIdx.y * 128, j0 = blockIdx.x * 128;
    if (j0 > i0 + 639) return;
    extern __shared__ float sm_[];
    uint32_t sb = smem_u32(sm_);
    int t = threadIdx.x, wid = t >> 5, lane = t & 31, g = lane >> 2, q = lane & 3;
    int z = blockIdx.z, bb = z >> 4, hh = z & 15;
    int wm = (wid >> 2) * 64, wn = (wid & 3) * 32;

    int lrow = t >> 1, lkc = (t & 1) * 8;
    const float* Ag = Qu + (size_t)z * QLEN * HDIM + (size_t)(i0 + lrow) * HDIM + lkc;
    const float* Bg = qkv + ((size_t)(j0 + lrow) * 4 + bb) * 3072 + 1024 + hh * 64 + lkc;
    uint32_t as_s = sb + (uint32_t)((lrow * SMP + lkc) * 4);
    uint32_t bs_s = as_s + 128 * SMP * 4;

    float acc[4][4][4];
    #pragma unroll
    for (int i = 0; i < 4; i++)
        #pragma unroll
        for (int j = 0; j < 4; j++)
            #pragma unroll
            for (int v = 0; v < 4; v++) acc[i][j][v] = 0.f;

    auto issue = [&](int c) {
        uint32_t off = (uint32_t)(c % 3) * STG_NT * 4;
        const float* ag = Ag + c * 16;
        const float* bg = Bg + c * 16;
        cpa16(as_s + off, ag); cpa16(as_s + off + 16, ag + 4);
        cpa16(bs_s + off, bg); cpa16(bs_s + off + 16, bg + 4);
        cpcommit();
    };
    issue(0); issue(1);

    #pragma unroll
    for (int c = 0; c < 4; c++) {
        if (c + 1 < 4) asm volatile("cp.async.wait_group 1;" ::: "memory");
        else           asm volatile("cp.async.wait_group 0;" ::: "memory");
        __syncthreads();
        if (c + 2 < 4) issue(c + 2);

        const float* As = sm_ + (c % 3) * STG_NT;
        const float* Bs = As + 128 * SMP;
        #pragma unroll
        for (int ks = 0; ks < 16; ks += 8) {
            uint32_t af[4][4], bf[4][2];
            #pragma unroll
            for (int mt = 0; mt < 4; mt++) {
                int r = wm + mt * 16 + g;
                af[mt][0] = tf32u(As[r * SMP + ks + q]);
                af[mt][1] = tf32u(As[(r + 8) * SMP + ks + q]);
                af[mt][2] = tf32u(As[r * SMP + ks + q + 4]);
                af[mt][3] = tf32u(As[(r + 8) * SMP + ks + q + 4]);
            }
            #pragma unroll
            for (int nt = 0; nt < 4; nt++) {
                int rn = wn + nt * 8 + g;
                bf[nt][0] = tf32u(Bs[rn * SMP + ks + q]);
                bf[nt][1] = tf32u(Bs[rn * SMP + ks + q + 4]);
            }
            #pragma unroll
            for (int mt = 0; mt < 4; mt++)
                #pragma unroll
                for (int nt = 0; nt < 4; nt++)
                    mma_tf32(acc[mt][nt], af[mt], bf[nt]);
        }
    }

    const __nv_bfloat16* BDz = BD + (size_t)z * QLEN * KLENC;
    __nv_bfloat16* Sz = S + (size_t)z * QLEN * KLENC;
    float* rz = rsum + (size_t)z * QLEN;
    #pragma unroll
    for (int mt = 0; mt < 4; mt++) {
        int r0i = i0 + wm + mt * 16 + g;
        int r1i = r0i + 8;
        float s0 = 0.f, s1 = 0.f;
        const __nv_bfloat16* bd0 = BDz + (size_t)r0i * KLENC + (1023 - r0i);
        const __nv_bfloat16* bd1 = BDz + (size_t)r1i * KLENC + (1023 - r1i);
        #pragma unroll
        for (int nt = 0; nt < 4; nt++) {
            int col = j0 + wn + nt * 8 + q * 2;
            int v00 = (col     <= r0i + 512);
            int v01 = (col + 1 <= r0i + 512);
            int v10 = (col     <= r1i + 512);
            int v11 = (col + 1 <= r1i + 512);
            float p00 = v00 ? __expf((acc[mt][nt][0] + __bfloat162float(bd0[col]))     * ATT_SCALE) : 0.f;
            float p01 = v01 ? __expf((acc[mt][nt][1] + __bfloat162float(bd0[col + 1])) * ATT_SCALE) : 0.f;
            float p10 = v10 ? __expf((acc[mt][nt][2] + __bfloat162float(bd1[col]))     * ATT_SCALE) : 0.f;
            float p11 = v11 ? __expf((acc[mt][nt][3] + __bfloat162float(bd1[col + 1])) * ATT_SCALE) : 0.f;
            // round to bf16 BEFORE summing so normalization matches pv's operand
            __nv_bfloat162 q0 = __floats2bfloat162_rn(p00, p01);
            __nv_bfloat162 q1 = __floats2bfloat162_rn(p10, p11);
            *(uint32_t*)&Sz[(size_t)r0i * KLENC + col] = *(uint32_t*)&q0;
            *(uint32_t*)&Sz[(size_t)r1i * KLENC + col] = *(uint32_t*)&q1;
            s0 += __bfloat162float(q0.x) + __bfloat162float(q0.y);
            s1 += __bfloat162float(q1.x) + __bfloat162float(q1.y);
        }
        s0 += __shfl_xor_sync(0xffffffffu, s0, 1);
        s0 += __shfl_xor_sync(0xffffffffu, s0, 2);
        s1 += __shfl_xor_sync(0xffffffffu, s1, 1);
        s1 += __shfl_xor_sync(0xffffffffu, s1, 2);
        if (q == 0) {
            atomicAdd(&rz[r0i], s0);
            atomicAdd(&rz[r1i], s1);
        }
    }
}

// ============ PV: ctx = (P(bf16) @ V) / rsum ============
// A-tile: 128 rows x 16 bf16, pitch 24 halves (48B rows, 16B-aligned, conflict-free)
#define PAH 24
#define VPV 72
#define PV_A_BYTES (128 * PAH * 2)               // 6144
#define STG_PV_B (PV_A_BYTES + 16 * VPV * 4)     // 10752
#define PV_SMEM (3 * STG_PV_B)                   // 32256

__global__ __launch_bounds__(256, 2)
void pv_mma(const __nv_bfloat16* __restrict__ S, const float* __restrict__ qkv,
            const float* __restrict__ rsum, float* __restrict__ ctx)
{
    extern __shared__ float sm_[];
    uint32_t sb = smem_u32(sm_);
    int t = threadIdx.x, wid = t >> 5, lane = t & 31, g = lane >> 2, q = lane & 3;
    int i0 = (gridDim.x - 1 - blockIdx.x) * 128;   // longest-K blocks first
    int z = blockIdx.y, bb = z >> 4, hh = z & 15;
    int wm = (wid >> 1) * 32, wn = (wid & 1) * 32;

    const __nv_bfloat16* Ag = S + ((size_t)z * QLEN + i0 + (t >> 1)) * KLENC + (t & 1) * 8;
    uint32_t as_s = sb + (uint32_t)(((t >> 1) * PAH + (t & 1) * 8) * 2);
    int vrow = (t & 127) >> 3, vcol = (t & 7) * 8;
    uint32_t vs_s = sb + (uint32_t)(PV_A_BYTES + (vrow * VPV + vcol) * 4);

    float acc[2][4][4];
    #pragma unroll
    for (int i = 0; i < 2; i++)
        #pragma unroll
        for (int j = 0; j < 4; j++)
            #pragma unroll
            for (int v = 0; v < 4; v++) acc[i][j][v] = 0.f;

    int jlim = i0 + 640; if (jlim > KLENC) jlim = KLENC;
    int NC = jlim >> 4;

    auto issue = [&](int c) {
        uint32_t off = (uint32_t)(c % 3) * STG_PV_B;
        cpa16(as_s + off, Ag + c * 16);            // 8 bf16 = 16B
        if (t < 128) {
            const float* vg = qkv + ((size_t)((c * 16 + vrow) * 4 + bb)) * 3072 + 2048 + hh * 64 + vcol;
            cpa16(vs_s + off, vg); cpa16(vs_s + off + 16, vg + 4);
        }
        cpcommit();
    };
    issue(0);
    if (NC > 1) issue(1);

    for (int c = 0; c < NC; c++) {
        if (c + 1 < NC) asm volatile("cp.async.wait_group 1;" ::: "memory");
        else            asm volatile("cp.async.wait_group 0;" ::: "memory");
        __syncthreads();
        if (c + 2 < NC) issue(c + 2);

        const __nv_bfloat16* Ash =
            (const __nv_bfloat16*)((const char*)sm_ + (c % 3) * STG_PV_B);
        const float* Vs = (const float*)((const char*)sm_ + (c % 3) * STG_PV_B + PV_A_BYTES);
        #pragma unroll
        for (int ks = 0; ks < 16; ks += 8) {
            uint32_t af[2][4], bf[4][2];
            #pragma unroll
            for (int mt = 0; mt < 2; mt++) {
                int r = wm + mt * 16 + g;
                af[mt][0] = tf32u(__bfloat162float(Ash[r * PAH + ks + q]));
                af[mt][1] = tf32u(__bfloat162float(Ash[(r + 8) * PAH + ks + q]));
                af[mt][2] = tf32u(__bfloat162float(Ash[r * PAH + ks + q + 4]));
                af[mt][3] = tf32u(__bfloat162float(Ash[(r + 8) * PAH + ks + q + 4]));
            }
            #pragma unroll
            for (int nt = 0; nt < 4; nt++) {
                int n = wn + nt * 8 + g;
                bf[nt][0] = tf32u(Vs[(ks + q) * VPV + n]);
                bf[nt][1] = tf32u(Vs[(ks + q + 4) * VPV + n]);
            }
            #pragma unroll
            for (int mt = 0; mt < 2; mt++)
                #pragma unroll
                for (int nt = 0; nt < 4; nt++)
                    mma_tf32(acc[mt][nt], af[mt], bf[nt]);
        }
    }

    const float* rz = rsum + (size_t)z * QLEN;
    #pragma unroll
    for (int mt = 0; mt < 2; mt++) {
        int m = i0 + wm + mt * 16 + g;
        float inv0 = 1.f / rz[m];
        float inv1 = 1.f / rz[m + 8];
        #pragma unroll
        for (int nt = 0; nt < 4; nt++) {
            int d = wn + nt * 8 + q * 2;
            size_t o0 = ((size_t)m * 4 + bb) * 1024 + hh * 64 + d;
            size_t o1 = ((size_t)(m + 8) * 4 + bb) * 1024 + hh * 64 + d;
            *(float2*)&ctx[o0] = make_float2(acc[mt][nt][0] * inv0, acc[mt][nt][1] * inv0);
            *(float2*)&ctx[o1] = make_float2(acc[mt][nt][2] * inv1, acc[mt][nt][3] * inv1);
        }
    }
}

// ---------------- Qu/Qv prep ----------------
__global__ void quv_prep(const float* __restrict__ qkv, const float* __restrict__ u,
                         const float* __restrict__ v, float* __restrict__ Qu,
                         float* __restrict__ Qv)
{
    size_t idx = (size_t)blockIdx.x * 256 + threadIdx.x;
    int d = idx & 63;
    size_t row = idx >> 6;
    int i = row & 1023;
    int z = row >> 10, bb = z >> 4, hh = z & 15;
    float qv = qkv[((size_t)((MEMLEN + i) * 4 + bb)) * 3072 + hh * 64 + d];
    Qu[idx] = qv + u[hh * 64 + d];
    Qv[idx] = qv + v[hh * 64 + d];
}

// ---------------- layernorm ----------------
__device__ __forceinline__ float block_sum256(float v, float* red)
{
    #pragma unroll
    for (int o = 16; o; o >>= 1) v += __shfl_xor_sync(0xffffffffu, v, o);
    if ((threadIdx.x & 31) == 0) red[threadIdx.x >> 5] = v;
    __syncthreads();
    float s = 0.f;
    #pragma unroll
    for (int w = 0; w < 8; w++) s += red[w];
    __syncthreads();
    return s;
}

__global__ void ln_kernel(const float* __restrict__ A, const float* __restrict__ Bv,
                          const float* __restrict__ g, const float* __restrict__ be,
                          float* __restrict__ out)
{
    int row = blockIdx.x;
    int t = threadIdx.x;
    __shared__ float red[8];
    size_t base = (size_t)row * DMODEL;

    float x[4];
    float s = 0.f;
    #pragma unroll
    for (int r = 0; r < 4; r++) {
        int c = t + r * 256;
        x[r] = A[base + c] + Bv[base + c];
        s += x[r];
    }
    float mean = block_sum256(s, red) * (1.f / DMODEL);

    float q = 0.f;
    #pragma unroll
    for (int r = 0; r < 4; r++) {
        float d = x[r] - mean;
        q += d * d;
    }
    float var = block_sum256(q, red) * (1.f / DMODEL);
    float rstd = rsqrtf(var + 1e-5f);

    #pragma unroll
    for (int r = 0; r < 4; r++) {
        int c = t + r * 256;
        out[base + c] = (x[r] - mean) * rstd * g[c] + be[c];
    }
}

// ---------------- host orchestration ----------------
extern "C" void kernel_launch(void* const* d_in, const int* in_sizes, int n_in,
                              void* d_out, int out_size)
{
    (void)in_sizes; (void)out_size;
    int off = (n_in >= 17) ? 0 : -1;
    const float* inp   = (const float*)d_in[0];
    const float* r     = (const float*)d_in[1];
    const float* u     = (const float*)d_in[2];
    const float* v     = (const float*)d_in[3];
    const float* mem   = (const float*)d_in[4];
    const float* W_qkv = (const float*)d_in[6 + off];
    const float* W_r   = (const float*)d_in[7 + off];
    const float* W_o   = (const float*)d_in[8 + off];
    const float* ln1g  = (const float*)d_in[9 + off];
    const float* ln1b  = (const float*)d_in[10 + off];
    const float* ln2g  = (const float*)d_in[11 + off];
    const float* ln2b  = (const float*)d_in[12 + off];
    const float* W1    = (const float*)d_in[13 + off];
    const float* b1    = (const float*)d_in[14 + off];
    const float* W2    = (const float*)d_in[15 + off];
    const float* b2    = (const float*)d_in[16 + off];
    float* out = (float*)d_out;

    float *cat_p, *qkv_p, *rh_p, *Qu_p, *Qv_p, *rs_p, *ctx_p, *y_p, *x_p, *h_p, *y2_p;
    __nv_bfloat16 *S_p, *BD_p;
    cudaGetSymbolAddress((void**)&cat_p, g_cat);
    cudaGetSymbolAddress((void**)&qkv_p, g_qkv);
    cudaGetSymbolAddress((void**)&rh_p,  g_rh);
    cudaGetSymbolAddress((void**)&S_p,   g_S);
    cudaGetSymbolAddress((void**)&BD_p,  g_BD);
    cudaGetSymbolAddress((void**)&Qu_p,  g_Qu);
    cudaGetSymbolAddress((void**)&Qv_p,  g_Qv);
    cudaGetSymbolAddress((void**)&rs_p,  g_rsum);
    cudaGetSymbolAddress((void**)&ctx_p, g_ctx);
    cudaGetSymbolAddress((void**)&y_p,   g_y);
    cudaGetSymbolAddress((void**)&x_p,   g_x);
    cudaGetSymbolAddress((void**)&h_p,   g_h);
    cudaGetSymbolAddress((void**)&y2_p,  g_y2);

    cudaFuncSetAttribute(mm_nn,    cudaFuncAttributeMaxDynamicSharedMemorySize, NN_SMEM);
    cudaFuncSetAttribute(mm_nt_bf, cudaFuncAttributeMaxDynamicSharedMemorySize, NT_SMEM);
    cudaFuncSetAttribute(ac_fused, cudaFuncAttributeMaxDynamicSharedMemorySize, NT_SMEM);
    cudaFuncSetAttribute(pv_mma,   cudaFuncAttributeMaxDynamicSharedMemorySize, PV_SMEM);

    // cat = [mem; inputs]
    cudaMemcpyAsync(cat_p, mem, (size_t)MEMLEN * BATCH * DMODEL * sizeof(float),
                    cudaMemcpyDeviceToDevice);
    cudaMemcpyAsync(cat_p + (size_t)MEMLEN * BATCH * DMODEL, inp,
                    (size_t)QLEN * BATCH * DMODEL * sizeof(float),
                    cudaMemcpyDeviceToDevice);
    cudaMemsetAsync(rs_p, 0, (size_t)64 * QLEN * sizeof(float));

    dim3 blk(256);
    // qkv = cat @ W_qkv
    mm_nn<<<dim3(3072/128, 6144/128), blk, NN_SMEM>>>(
        cat_p, W_qkv, qkv_p, 6144, 3072, 1024, 1024, 3072, 3072, nullptr, 0);
    // r_h = r @ W_r
    mm_nn<<<dim3(1024/128, 1536/128), blk, NN_SMEM>>>(
        r, W_r, rh_p, 1536, 1024, 1024, 1024, 1024, 1024, nullptr, 0);
    // Qu/Qv prep
    quv_prep<<<(64 * QLEN * HDIM) / 256, 256>>>(qkv_p, u, v, Qu_p, Qv_p);
    // BD[z] = Qv @ rh[:, h*64:h*64+64]^T -> bf16, dead tiles skipped
    mm_nt_bf<<<dim3(1536/128, 1024/128, 64), blk, NT_SMEM>>>(
        Qv_p, rh_p, BD_p, 64, 1024, 1536,
        (long)1024*64, 64, (long)1024*1536, 769, 4);
    // P(bf16) = exp(mask(AC + shift(BD)) * scale), rowsum -> rsum
    ac_fused<<<dim3(1536/128, 1024/128, 64), blk, NT_SMEM>>>(
        Qu_p, qkv_p, BD_p, S_p, rs_p);
    // ctx = (P @ V) / rsum
    pv_mma<<<dim3(QLEN/128, 64), blk, PV_SMEM>>>(S_p, qkv_p, rs_p, ctx_p);
    // y = ctx @ W_o
    mm_nn<<<dim3(1024/128, 4096/128), blk, NN_SMEM>>>(
        ctx_p, W_o, y_p, 4096, 1024, 1024, 1024, 1024, 1024, nullptr, 0);
    ln_kernel<<<NROWS, 256>>>(inp, y_p, ln1g, ln1b, x_p);
    // h = relu(x @ W1 + b1)
    mm_nn<<<dim3(4096/128, 4096/128), blk, NN_SMEM>>>(
        x_p, W1, h_p, 4096, 4096, 1024, 1024, 4096, 4096, b1, 1);
    // y2 = h @ W2 + b2
    mm_nn<<<dim3(1024/128, 4096/128), blk, NN_SMEM>>>(
        h_p, W2, y2_p, 4096, 1024, 4096, 4096, 1024, 1024, b2, 0);
    ln_kernel<<<NROWS, 256>>>(x_p, y2_p, ln2g, ln2b, out);
}

// round 16
// speedup vs baseline: 1.8685x; 1.0658x over previous
#include <cuda_runtime.h>
#include <cuda_bf16.h>
#include <cstdint>
#include <math.h>

// ---------------- problem constants ----------------
#define QLEN    1024
#define BATCH   4
#define DMODEL  1024
#define NHEAD   16
#define HDIM    64
#define MEMLEN  512
#define KLENC   1536
#define MLPD    4096
#define ATT_SCALE 0.125f
#define NROWS   4096
#define KROWS   6144

// ---------------- scratch ----------------
__device__ __align__(16) float g_cat[(size_t)KROWS * DMODEL];
__device__ __align__(16) float g_qkv[(size_t)KROWS * 3 * DMODEL];
__device__ __align__(16) float g_rh [(size_t)KLENC * DMODEL];
__device__ __align__(16) __nv_bfloat16 g_S  [(size_t)64 * QLEN * KLENC];  // probs
__device__ __align__(16) __nv_bfloat16 g_BD [(size_t)64 * QLEN * KLENC];  // BD
__device__ __align__(16) __nv_bfloat16 g_Qu [(size_t)64 * QLEN * HDIM];
__device__ __align__(16) __nv_bfloat16 g_Qv [(size_t)64 * QLEN * HDIM];
__device__ __align__(16) __nv_bfloat16 g_K  [(size_t)KROWS * 1024];       // K heads, bf16
__device__ __align__(16) __nv_bfloat16 g_Vt [(size_t)64 * HDIM * KLENC];  // V transposed [z][d][j]
__device__ __align__(16) __nv_bfloat16 g_rhb[(size_t)KLENC * DMODEL];
__device__ __align__(16) float g_rsum[(size_t)64 * QLEN];
__device__ __align__(16) float g_ctx[(size_t)NROWS * DMODEL];
__device__ __align__(16) float g_y  [(size_t)NROWS * DMODEL];
__device__ __align__(16) float g_x  [(size_t)NROWS * DMODEL];
__device__ __align__(16) float g_h  [(size_t)NROWS * MLPD];
__device__ __align__(16) float g_y2 [(size_t)NROWS * DMODEL];

// ---------------- helpers ----------------
__device__ __forceinline__ uint32_t smem_u32(const void* p) {
    uint32_t a;
    asm("{ .reg .u64 t; cvta.to.shared.u64 t, %1; cvt.u32.u64 %0, t; }" : "=r"(a) : "l"(p));
    return a;
}
__device__ __forceinline__ uint32_t tf32u(float x) {
    uint32_t u;
    asm("cvt.rna.tf32.f32 %0, %1;" : "=r"(u) : "f"(x));
    return u;
}
__device__ __forceinline__ void cpa16(uint32_t s, const void* g) {
    asm volatile("cp.async.cg.shared.global [%0], [%1], 16;" :: "r"(s), "l"(g));
}
__device__ __forceinline__ void cpcommit() {
    asm volatile("cp.async.commit_group;" ::: "memory");
}
__device__ __forceinline__ void mma_tf32(float* c, const uint32_t* a, const uint32_t* b)
{
    asm volatile(
        "mma.sync.aligned.m16n8k8.row.col.f32.tf32.tf32.f32 "
        "{%0,%1,%2,%3}, {%4,%5,%6,%7}, {%8,%9}, {%0,%1,%2,%3};"
        : "+f"(c[0]), "+f"(c[1]), "+f"(c[2]), "+f"(c[3])
        : "r"(a[0]), "r"(a[1]), "r"(a[2]), "r"(a[3]), "r"(b[0]), "r"(b[1]));
}
__device__ __forceinline__ void mma_bf16(float* c, const uint32_t* a, const uint32_t* b)
{
    asm volatile(
        "mma.sync.aligned.m16n8k16.row.col.f32.bf16.bf16.f32 "
        "{%0,%1,%2,%3}, {%4,%5,%6,%7}, {%8,%9}, {%0,%1,%2,%3};"
        : "+f"(c[0]), "+f"(c[1]), "+f"(c[2]), "+f"(c[3])
        : "r"(a[0]), "r"(a[1]), "r"(a[2]), "r"(a[3]), "r"(b[0]), "r"(b[1]));
}
__device__ __forceinline__ uint32_t bf2pack(float lo, float hi) {
    __nv_bfloat162 p = __floats2bfloat162_rn(lo, hi);
    return *(uint32_t*)&p;
}

// ============ mm_nn: dense fp32/tf32 GEMM (R10 measured-best, unchanged) ============
#define SMP 20
#define BPN 136
#define STG_NN (128 * SMP + 16 * BPN)
#define NN_SMEM (3 * STG_NN * 4)

__global__ __launch_bounds__(256, 2)
void mm_nn(const float* __restrict__ A, const float* __restrict__ B, float* __restrict__ C,
           int M, int N, int K, int lda, int ldb, int ldc,
           const float* __restrict__ bias, int relu)
{
    extern __shared__ float sm_[];
    uint32_t sb = smem_u32(sm_);
    int t = threadIdx.x, wid = t >> 5, lane = t & 31, g = lane >> 2, q = lane & 3;
    int row0 = blockIdx.y * 128, col0 = blockIdx.x * 128;
    int wm = (wid >> 2) * 64, wn = (wid & 3) * 32;

    int lrow = t >> 1, lkc = (t & 1) * 8;
    int krow = t >> 4, ncol = (t & 15) * 8;
    const float* Ag = A + (size_t)(row0 + lrow) * lda + lkc;
    const float* Bg = B + (size_t)krow * ldb + col0 + ncol;
    uint32_t as_s = sb + (uint32_t)((lrow * SMP + lkc) * 4);
    uint32_t bs_s = sb + (uint32_t)((128 * SMP + krow * BPN + ncol) * 4);

    float acc[4][4][4];
    #pragma unroll
    for (int i = 0; i < 4; i++)
        #pragma unroll
        for (int j = 0; j < 4; j++)
            #pragma unroll
            for (int v = 0; v < 4; v++) acc[i][j][v] = 0.f;

    int NC = K >> 4;
    auto issue = [&](int c) {
        uint32_t off = (uint32_t)(c % 3) * STG_NN * 4;
        const float* ag = Ag + c * 16;
        const float* bg = Bg + (size_t)c * 16 * ldb;
        cpa16(as_s + off, ag);       cpa16(as_s + off + 16, ag + 4);
        cpa16(bs_s + off, bg);       cpa16(bs_s + off + 16, bg + 4);
        cpcommit();
    };
    issue(0);
    if (NC > 1) issue(1);

    for (int c = 0; c < NC; c++) {
        if (c + 1 < NC) asm volatile("cp.async.wait_group 1;" ::: "memory");
        else            asm volatile("cp.async.wait_group 0;" ::: "memory");
        __syncthreads();
        if (c + 2 < NC) issue(c + 2);

        const float* As = sm_ + (c % 3) * STG_NN;
        const float* Bs = As + 128 * SMP;
        #pragma unroll
        for (int ks = 0; ks < 16; ks += 8) {
            uint32_t af[4][4], bf[4][2];
            #pragma unroll
            for (int mt = 0; mt < 4; mt++) {
                int r = wm + mt * 16 + g;
                af[mt][0] = tf32u(As[r * SMP + ks + q]);
                af[mt][1] = tf32u(As[(r + 8) * SMP + ks + q]);
                af[mt][2] = tf32u(As[r * SMP + ks + q + 4]);
                af[mt][3] = tf32u(As[(r + 8) * SMP + ks + q + 4]);
            }
            #pragma unroll
            for (int nt = 0; nt < 4; nt++) {
                int n = wn + nt * 8 + g;
                bf[nt][0] = tf32u(Bs[(ks + q) * BPN + n]);
                bf[nt][1] = tf32u(Bs[(ks + q + 4) * BPN + n]);
            }
            #pragma unroll
            for (int mt = 0; mt < 4; mt++)
                #pragma unroll
                for (int nt = 0; nt < 4; nt++)
                    mma_tf32(acc[mt][nt], af[mt], bf[nt]);
        }
    }

    #pragma unroll
    for (int mt = 0; mt < 4; mt++) {
        int row = row0 + wm + mt * 16 + g;
        #pragma unroll
        for (int nt = 0; nt < 4; nt++) {
            int col = col0 + wn + nt * 8 + q * 2;
            float b0 = bias ? bias[col] : 0.f;
            float b1 = bias ? bias[col + 1] : 0.f;
            float o0 = acc[mt][nt][0] + b0, o1 = acc[mt][nt][1] + b1;
            float o2 = acc[mt][nt][2] + b0, o3 = acc[mt][nt][3] + b1;
            if (relu) {
                o0 = fmaxf(o0, 0.f); o1 = fmaxf(o1, 0.f);
                o2 = fmaxf(o2, 0.f); o3 = fmaxf(o3, 0.f);
            }
            *(float2*)&C[(size_t)row * ldc + col]       = make_float2(o0, o1);
            *(float2*)&C[(size_t)(row + 8) * ldc + col] = make_float2(o2, o3);
        }
    }
}

// ============ bf16 NT GEMM bits (BD / AC / PV) ============
// tiles: A 128 rows x 32 k (bf16, pitch 40 halves); B rows x 32 k (pitch 40)
#define PAH 40
#define STG_BD (2 * 128 * PAH * 2)               // 20480 B/stage
#define BD_SMEM (3 * STG_BD)                     // 61440

// BD[z] = Qv @ rhb[:, h*64:+64]^T -> bf16
__global__ __launch_bounds__(256, 2)
void bd16(const __nv_bfloat16* __restrict__ Qv, const __nv_bfloat16* __restrict__ rhb,
          __nv_bfloat16* __restrict__ BD, int skipSum)
{
    int row0 = blockIdx.y * 128, col0 = blockIdx.x * 128;
    if (row0 + col0 < skipSum) return;
    extern __shared__ char smc[];
    uint32_t sb = smem_u32(smc);
    int t = threadIdx.x, wid = t >> 5, lane = t & 31, g = lane >> 2, q = lane & 3;
    int z = blockIdx.z, hh = z & 15;
    int wm = (wid >> 2) * 64, wn = (wid & 3) * 32;

    int lrow = t >> 1, lo = (t & 1) * 16;        // halves
    const __nv_bfloat16* Ag = Qv + (size_t)z * QLEN * HDIM + (size_t)(row0 + lrow) * 64 + lo;
    const __nv_bfloat16* Bg = rhb + (size_t)(col0 + lrow) * 1024 + hh * 64 + lo;
    uint32_t as_s = sb + (uint32_t)((lrow * PAH + lo) * 2);
    uint32_t bs_s = as_s + 128 * PAH * 2;

    float acc[4][4][4];
    #pragma unroll
    for (int i = 0; i < 4; i++)
        #pragma unroll
        for (int j = 0; j < 4; j++)
            #pragma unroll
            for (int v = 0; v < 4; v++) acc[i][j][v] = 0.f;

    auto issue = [&](int c) {
        uint32_t off = (uint32_t)(c % 3) * STG_BD;
        cpa16(as_s + off, Ag + c * 32); cpa16(as_s + off + 16, Ag + c * 32 + 8);
        cpa16(bs_s + off, Bg + c * 32); cpa16(bs_s + off + 16, Bg + c * 32 + 8);
        cpcommit();
    };
    issue(0); issue(1);

    #pragma unroll
    for (int c = 0; c < 2; c++) {                 // K=64, chunks of 32
        if (c == 0) asm volatile("cp.async.wait_group 1;" ::: "memory");
        else        asm volatile("cp.async.wait_group 0;" ::: "memory");
        __syncthreads();

        const __nv_bfloat16* As = (const __nv_bfloat16*)(smc + (c % 3) * STG_BD);
        const __nv_bfloat16* Bs = As + 128 * PAH;
        #pragma unroll
        for (int ks = 0; ks < 32; ks += 16) {
            uint32_t af[4][4], bf[4][2];
            #pragma unroll
            for (int mt = 0; mt < 4; mt++) {
                int r = wm + mt * 16 + g;
                af[mt][0] = *(const uint32_t*)&As[r * PAH + ks + 2 * q];
                af[mt][1] = *(const uint32_t*)&As[(r + 8) * PAH + ks + 2 * q];
                af[mt][2] = *(const uint32_t*)&As[r * PAH + ks + 2 * q + 8];
                af[mt][3] = *(const uint32_t*)&As[(r + 8) * PAH + ks + 2 * q + 8];
            }
            #pragma unroll
            for (int nt = 0; nt < 4; nt++) {
                int rn = wn + nt * 8 + g;
                bf[nt][0] = *(const uint32_t*)&Bs[rn * PAH + ks + 2 * q];
                bf[nt][1] = *(const uint32_t*)&Bs[rn * PAH + ks + 2 * q + 8];
            }
            #pragma unroll
            for (int mt = 0; mt < 4; mt++)
                #pragma unroll
                for (int nt = 0; nt < 4; nt++)
                    mma_bf16(acc[mt][nt], af[mt], bf[nt]);
        }
    }

    __nv_bfloat16* Cz = BD + (size_t)z * QLEN * KLENC;
    #pragma unroll
    for (int mt = 0; mt < 4; mt++) {
        int row = row0 + wm + mt * 16 + g;
        #pragma unroll
        for (int nt = 0; nt < 4; nt++) {
            int col = col0 + wn + nt * 8 + q * 2;
            *(uint32_t*)&Cz[(size_t)row * KLENC + col] =
                bf2pack(acc[mt][nt][0], acc[mt][nt][1]);
            *(uint32_t*)&Cz[(size_t)(row + 8) * KLENC + col] =
                bf2pack(acc[mt][nt][2], acc[mt][nt][3]);
        }
    }
}

// AC + shift(BD) + mask + exp -> P(bf16) + rowsum
__global__ __launch_bounds__(256, 2)
void ac16(const __nv_bfloat16* __restrict__ Qu, const __nv_bfloat16* __restrict__ Kb,
          const __nv_bfloat16* __restrict__ BD, __nv_bfloat16* __restrict__ S,
          float* __restrict__ rsum)
{
    int i0 = blockIdx.y * 128, j0 = blockIdx.x * 128;
    if (j0 > i0 + 639) return;
    extern __shared__ char smc[];
    uint32_t sb = smem_u32(smc);
    int t = threadIdx.x, wid = t >> 5, lane = t & 31, g = lane >> 2, q = lane & 3;
    int z = blockIdx.z, bb = z >> 4, hh = z & 15;
    int wm = (wid >> 2) * 64, wn = (wid & 3) * 32;

    int lrow = t >> 1, lo = (t & 1) * 16;
    const __nv_bfloat16* Ag = Qu + (size_t)z * QLEN * HDIM + (size_t)(i0 + lrow) * 64 + lo;
    const __nv_bfloat16* Bg = Kb + ((size_t)(j0 + lrow) * 4 + bb) * 1024 + hh * 64 + lo;
    uint32_t as_s = sb + (uint32_t)((lrow * PAH + lo) * 2);
    uint32_t bs_s = as_s + 128 * PAH * 2;

    float acc[4][4][4];
    #pragma unroll
    for (int i = 0; i < 4; i++)
        #pragma unroll
        for (int j = 0; j < 4; j++)
            #pragma unroll
            for (int v = 0; v < 4; v++) acc[i][j][v] = 0.f;

    auto issue = [&](int c) {
        uint32_t off = (uint32_t)(c % 3) * STG_BD;
        cpa16(as_s + off, Ag + c * 32); cpa16(as_s + off + 16, Ag + c * 32 + 8);
        cpa16(bs_s + off, Bg + c * 32); cpa16(bs_s + off + 16, Bg + c * 32 + 8);
        cpcommit();
    };
    issue(0); issue(1);

    #pragma unroll
    for (int c = 0; c < 2; c++) {
        if (c == 0) asm volatile("cp.async.wait_group 1;" ::: "memory");
        else        asm volatile("cp.async.wait_group 0;" ::: "memory");
        __syncthreads();

        const __nv_bfloat16* As = (const __nv_bfloat16*)(smc + (c % 3) * STG_BD);
        const __nv_bfloat16* Bs = As + 128 * PAH;
        #pragma unroll
        for (int ks = 0; ks < 32; ks += 16) {
            uint32_t af[4][4], bf[4][2];
            #pragma unroll
            for (int mt = 0; mt < 4; mt++) {
                int r = wm + mt * 16 + g;
                af[mt][0] = *(const uint32_t*)&As[r * PAH + ks + 2 * q];
                af[mt][1] = *(const uint32_t*)&As[(r + 8) * PAH + ks + 2 * q];
                af[mt][2] = *(const uint32_t*)&As[r * PAH + ks + 2 * q + 8];
                af[mt][3] = *(const uint32_t*)&As[(r + 8) * PAH + ks + 2 * q + 8];
            }
            #pragma unroll
            for (int nt = 0; nt < 4; nt++) {
                int rn = wn + nt * 8 + g;
                bf[nt][0] = *(const uint32_t*)&Bs[rn * PAH + ks + 2 * q];
                bf[nt][1] = *(const uint32_t*)&Bs[rn * PAH + ks + 2 * q + 8];
            }
            #pragma unroll
            for (int mt = 0; mt < 4; mt++)
                #pragma unroll
                for (int nt = 0; nt < 4; nt++)
                    mma_bf16(acc[mt][nt], af[mt], bf[nt]);
        }
    }

    const __nv_bfloat16* BDz = BD + (size_t)z * QLEN * KLENC;
    __nv_bfloat16* Sz = S + (size_t)z * QLEN * KLENC;
    float* rz = rsum + (size_t)z * QLEN;
    #pragma unroll
    for (int mt = 0; mt < 4; mt++) {
        int r0i = i0 + wm + mt * 16 + g;
        int r1i = r0i + 8;
        float s0 = 0.f, s1 = 0.f;
        const __nv_bfloat16* bd0 = BDz + (size_t)r0i * KLENC + (1023 - r0i);
        const __nv_bfloat16* bd1 = BDz + (size_t)r1i * KLENC + (1023 - r1i);
        #pragma unroll
        for (int nt = 0; nt < 4; nt++) {
            int col = j0 + wn + nt * 8 + q * 2;
            int v00 = (col     <= r0i + 512);
            int v01 = (col + 1 <= r0i + 512);
            int v10 = (col     <= r1i + 512);
            int v11 = (col + 1 <= r1i + 512);
            float p00 = v00 ? __expf((acc[mt][nt][0] + __bfloat162float(bd0[col]))     * ATT_SCALE) : 0.f;
            float p01 = v01 ? __expf((acc[mt][nt][1] + __bfloat162float(bd0[col + 1])) * ATT_SCALE) : 0.f;
            float p10 = v10 ? __expf((acc[mt][nt][2] + __bfloat162float(bd1[col]))     * ATT_SCALE) : 0.f;
            float p11 = v11 ? __expf((acc[mt][nt][3] + __bfloat162float(bd1[col + 1])) * ATT_SCALE) : 0.f;
            __nv_bfloat162 q0 = __floats2bfloat162_rn(p00, p01);
            __nv_bfloat162 q1 = __floats2bfloat162_rn(p10, p11);
            *(uint32_t*)&Sz[(size_t)r0i * KLENC + col] = *(uint32_t*)&q0;
            *(uint32_t*)&Sz[(size_t)r1i * KLENC + col] = *(uint32_t*)&q1;
            s0 += __bfloat162float(q0.x) + __bfloat162float(q0.y);
            s1 += __bfloat162float(q1.x) + __bfloat162float(q1.y);
        }
        s0 += __shfl_xor_sync(0xffffffffu, s0, 1);
        s0 += __shfl_xor_sync(0xffffffffu, s0, 2);
        s1 += __shfl_xor_sync(0xffffffffu, s1, 1);
        s1 += __shfl_xor_sync(0xffffffffu, s1, 2);
        if (q == 0) {
            atomicAdd(&rz[r0i], s0);
            atomicAdd(&rz[r1i], s1);
        }
    }
}

// PV: ctx = (P @ Vt^T) / rsum, bf16 operands; chunks of 32 j, 3-stage ring
#define STG_PV (128 * PAH * 2 + 64 * PAH * 2)    // 15360 B
#define PV_SMEM (3 * STG_PV)                     // 46080

__global__ __launch_bounds__(256, 2)
void pv16(const __nv_bfloat16* __restrict__ S, const __nv_bfloat16* __restrict__ Vt,
          const float* __restrict__ rsum, float* __restrict__ ctx)
{
    extern __shared__ char smc[];
    uint32_t sb = smem_u32(smc);
    int t = threadIdx.x, wid = t >> 5, lane = t & 31, g = lane >> 2, q = lane & 3;
    int i0 = (gridDim.x - 1 - blockIdx.x) * 128;   // longest-K first
    int z = blockIdx.y, bb = z >> 4, hh = z & 15;
    int wm = (wid >> 1) * 32, wn = (wid & 1) * 32;

    int lrow = t >> 1, lo = (t & 1) * 16;
    const __nv_bfloat16* Ag = S + ((size_t)z * QLEN + i0 + lrow) * KLENC + lo;
    uint32_t as_s = sb + (uint32_t)((lrow * PAH + lo) * 2);
    // Vt loader: t<128 -> 64 rows(d) x 32 halves
    int vrow = (t & 127) >> 1, vlo = (t & 1) * 16;
    const __nv_bfloat16* Bg = Vt + ((size_t)z * 64 + vrow) * KLENC + vlo;
    uint32_t bs_s = sb + (uint32_t)(128 * PAH * 2 + (vrow * PAH + vlo) * 2);

    float acc[2][4][4];
    #pragma unroll
    for (int i = 0; i < 2; i++)
        #pragma unroll
        for (int j = 0; j < 4; j++)
            #pragma unroll
            for (int v = 0; v < 4; v++) acc[i][j][v] = 0.f;

    int jlim = i0 + 640; if (jlim > KLENC) jlim = KLENC;
    int NC = jlim >> 5;

    auto issue = [&](int c) {
        uint32_t off = (uint32_t)(c % 3) * STG_PV;
        cpa16(as_s + off, Ag + c * 32); cpa16(as_s + off + 16, Ag + c * 32 + 8);
        if (t < 128) {
            cpa16(bs_s + off, Bg + c * 32); cpa16(bs_s + off + 16, Bg + c * 32 + 8);
        }
        cpcommit();
    };
    issue(0);
    if (NC > 1) issue(1);

    for (int c = 0; c < NC; c++) {
        if (c + 1 < NC) asm volatile("cp.async.wait_group 1;" ::: "memory");
        else            asm volatile("cp.async.wait_group 0;" ::: "memory");
        __syncthreads();
        if (c + 2 < NC) issue(c + 2);

        const __nv_bfloat16* As = (const __nv_bfloat16*)(smc + (c % 3) * STG_PV);
        const __nv_bfloat16* Bs = As + 128 * PAH;
        #pragma unroll
        for (int ks = 0; ks < 32; ks += 16) {
            uint32_t af[2][4], bf[4][2];
            #pragma unroll
            for (int mt = 0; mt < 2; mt++) {
                int r = wm + mt * 16 + g;
                af[mt][0] = *(const uint32_t*)&As[r * PAH + ks + 2 * q];
                af[mt][1] = *(const uint32_t*)&As[(r + 8) * PAH + ks + 2 * q];
                af[mt][2] = *(const uint32_t*)&As[r * PAH + ks + 2 * q + 8];
                af[mt][3] = *(const uint32_t*)&As[(r + 8) * PAH + ks + 2 * q + 8];
            }
            #pragma unroll
            for (int nt = 0; nt < 4; nt++) {
                int n = wn + nt * 8 + g;
                bf[nt][0] = *(const uint32_t*)&Bs[n * PAH + ks + 2 * q];
                bf[nt][1] = *(const uint32_t*)&Bs[n * PAH + ks + 2 * q + 8];
            }
            #pragma unroll
            for (int mt = 0; mt < 2; mt++)
                #pragma unroll
                for (int nt = 0; nt < 4; nt++)
                    mma_bf16(acc[mt][nt], af[mt], bf[nt]);
        }
    }

    const float* rz = rsum + (size_t)z * QLEN;
    #pragma unroll
    for (int mt = 0; mt < 2; mt++) {
        int m = i0 + wm + mt * 16 + g;
        float inv0 = 1.f / rz[m];
        float inv1 = 1.f / rz[m + 8];
        #pragma unroll
        for (int nt = 0; nt < 4; nt++) {
            int d = wn + nt * 8 + q * 2;
            size_t o0 = ((size_t)m * 4 + bb) * 1024 + hh * 64 + d;
            size_t o1 = ((size_t)(m + 8) * 4 + bb) * 1024 + hh * 64 + d;
            *(float2*)&ctx[o0] = make_float2(acc[mt][nt][0] * inv0, acc[mt][nt][1] * inv0);
            *(float2*)&ctx[o1] = make_float2(acc[mt][nt][2] * inv1, acc[mt][nt][3] * inv1);
        }
    }
}

// ---------------- converts ----------------
__global__ void quv_prep(const float* __restrict__ qkv, const float* __restrict__ u,
                         const float* __restrict__ v, __nv_bfloat16* __restrict__ Qu,
                         __nv_bfloat16* __restrict__ Qv)
{
    size_t idx = (size_t)blockIdx.x * 256 + threadIdx.x;
    int d = idx & 63;
    size_t row = idx >> 6;
    int i = row & 1023;
    int z = row >> 10, bb = (int)(z >> 4), hh = (int)(z & 15);
    float qv = qkv[((size_t)((MEMLEN + i) * 4 + bb)) * 3072 + hh * 64 + d];
    Qu[idx] = __float2bfloat16(qv + u[hh * 64 + d]);
    Qv[idx] = __float2bfloat16(qv + v[hh * 64 + d]);
}

__global__ void k_conv(const float* __restrict__ qkv, __nv_bfloat16* __restrict__ Kb)
{
    size_t base = ((size_t)blockIdx.x * 256 + threadIdx.x) * 4;   // 6144*1024 total
    size_t row = base >> 10; int c = (int)(base & 1023);
    float4 vl = *(const float4*)&qkv[row * 3072 + 1024 + c];
    *(uint32_t*)&Kb[base]     = bf2pack(vl.x, vl.y);
    *(uint32_t*)&Kb[base + 2] = bf2pack(vl.z, vl.w);
}

__global__ void rh_conv(const float* __restrict__ rh, __nv_bfloat16* __restrict__ rhb)
{
    size_t base = ((size_t)blockIdx.x * 256 + threadIdx.x) * 4;   // 1536*1024 total
    float4 vl = *(const float4*)&rh[base];
    *(uint32_t*)&rhb[base]     = bf2pack(vl.x, vl.y);
    *(uint32_t*)&rhb[base + 2] = bf2pack(vl.z, vl.w);
}

__global__ void vt_conv(const float* __restrict__ qkv, __nv_bfloat16* __restrict__ Vt)
{
    __shared__ float tile[32][33];
    int j0 = blockIdx.x * 32;
    int z = blockIdx.y, bb = z >> 4, hh = z & 15;
    int tx = threadIdx.x, ty = threadIdx.y;
    for (int dsub = 0; dsub < 64; dsub += 32) {
        __syncthreads();
        #pragma unroll
        for (int i = 0; i < 32; i += 8) {
            int jj = ty + i;
            tile[jj][tx] = qkv[((size_t)(j0 + jj) * 4 + bb) * 3072 + 2048 + hh * 64 + dsub + tx];
        }
        __syncthreads();
        #pragma unroll
        for (int i = 0; i < 32; i += 8) {
            int dd = ty + i;
            Vt[((size_t)z * 64 + dsub + dd) * KLENC + j0 + tx] = __float2bfloat16(tile[tx][dd]);
        }
    }
}

// ---------------- layernorm ----------------
__device__ __forceinline__ float block_sum256(float v, float* red)
{
    #pragma unroll
    for (int o = 16; o; o >>= 1) v += __shfl_xor_sync(0xffffffffu, v, o);
    if ((threadIdx.x & 31) == 0) red[threadIdx.x >> 5] = v;
    __syncthreads();
    float s = 0.f;
    #pragma unroll
    for (int w = 0; w < 8; w++) s += red[w];
    __syncthreads();
    return s;
}

__global__ void ln_kernel(const float* __restrict__ A, const float* __restrict__ Bv,
                          const float* __restrict__ g, const float* __restrict__ be,
                          float* __restrict__ out)
{
    int row = blockIdx.x;
    int t = threadIdx.x;
    __shared__ float red[8];
    size_t base = (size_t)row * DMODEL;

    float x[4];
    float s = 0.f;
    #pragma unroll
    for (int r = 0; r < 4; r++) {
        int c = t + r * 256;
        x[r] = A[base + c] + Bv[base + c];
        s += x[r];
    }
    float mean = block_sum256(s, red) * (1.f / DMODEL);

    float q = 0.f;
    #pragma unroll
    for (int r = 0; r < 4; r++) {
        float d = x[r] - mean;
        q += d * d;
    }
    float var = block_sum256(q, red) * (1.f / DMODEL);
    float rstd = rsqrtf(var + 1e-5f);

    #pragma unroll
    for (int r = 0; r < 4; r++) {
        int c = t + r * 256;
        out[base + c] = (x[r] - mean) * rstd * g[c] + be[c];
    }
}

// ---------------- host orchestration ----------------
extern "C" void kernel_launch(void* const* d_in, const int* in_sizes, int n_in,
                              void* d_out, int out_size)
{
    (void)in_sizes; (void)out_size;
    int off = (n_in >= 17) ? 0 : -1;
    const float* inp   = (const float*)d_in[0];
    const float* r     = (const float*)d_in[1];
    const float* u     = (const float*)d_in[2];
    const float* v     = (const float*)d_in[3];
    const float* mem   = (const float*)d_in[4];
    const float* W_qkv = (const float*)d_in[6 + off];
    const float* W_r   = (const float*)d_in[7 + off];
    const float* W_o   = (const float*)d_in[8 + off];
    const float* ln1g  = (const float*)d_in[9 + off];
    const float* ln1b  = (const float*)d_in[10 + off];
    const float* ln2g  = (const float*)d_in[11 + off];
    const float* ln2b  = (const float*)d_in[12 + off];
    const float* W1    = (const float*)d_in[13 + off];
    const float* b1    = (const float*)d_in[14 + off];
    const float* W2    = (const float*)d_in[15 + off];
    const float* b2    = (const float*)d_in[16 + off];
    float* out = (float*)d_out;

    float *cat_p, *qkv_p, *rh_p, *rs_p, *ctx_p, *y_p, *x_p, *h_p, *y2_p;
    __nv_bfloat16 *S_p, *BD_p, *Qu_p, *Qv_p, *K_p, *Vt_p, *rhb_p;
    cudaGetSymbolAddress((void**)&cat_p, g_cat);
    cudaGetSymbolAddress((void**)&qkv_p, g_qkv);
    cudaGetSymbolAddress((void**)&rh_p,  g_rh);
    cudaGetSymbolAddress((void**)&S_p,   g_S);
    cudaGetSymbolAddress((void**)&BD_p,  g_BD);
    cudaGetSymbolAddress((void**)&Qu_p,  g_Qu);
    cudaGetSymbolAddress((void**)&Qv_p,  g_Qv);
    cudaGetSymbolAddress((void**)&K_p,   g_K);
    cudaGetSymbolAddress((void**)&Vt_p,  g_Vt);
    cudaGetSymbolAddress((void**)&rhb_p, g_rhb);
    cudaGetSymbolAddress((void**)&rs_p,  g_rsum);
    cudaGetSymbolAddress((void**)&ctx_p, g_ctx);
    cudaGetSymbolAddress((void**)&y_p,   g_y);
    cudaGetSymbolAddress((void**)&x_p,   g_x);
    cudaGetSymbolAddress((void**)&h_p,   g_h);
    cudaGetSymbolAddress((void**)&y2_p,  g_y2);

    cudaFuncSetAttribute(mm_nn, cudaFuncAttributeMaxDynamicSharedMemorySize, NN_SMEM);
    cudaFuncSetAttribute(bd16,  cudaFuncAttributeMaxDynamicSharedMemorySize, BD_SMEM);
    cudaFuncSetAttribute(ac16,  cudaFuncAttributeMaxDynamicSharedMemorySize, BD_SMEM);
    cudaFuncSetAttribute(pv16,  cudaFuncAttributeMaxDynamicSharedMemorySize, PV_SMEM);

    // cat = [mem; inputs]
    cudaMemcpyAsync(cat_p, mem, (size_t)MEMLEN * BATCH * DMODEL * sizeof(float),
                    cudaMemcpyDeviceToDevice);
    cudaMemcpyAsync(cat_p + (size_t)MEMLEN * BATCH * DMODEL, inp,
                    (size_t)QLEN * BATCH * DMODEL * sizeof(float),
                    cudaMemcpyDeviceToDevice);
    cudaMemsetAsync(rs_p, 0, (size_t)64 * QLEN * sizeof(float));

    dim3 blk(256);
    // qkv = cat @ W_qkv
    mm_nn<<<dim3(3072/128, 6144/128), blk, NN_SMEM>>>(
        cat_p, W_qkv, qkv_p, 6144, 3072, 1024, 1024, 3072, 3072, nullptr, 0);
    // r_h = r @ W_r
    mm_nn<<<dim3(1024/128, 1536/128), blk, NN_SMEM>>>(
        r, W_r, rh_p, 1536, 1024, 1024, 1024, 1024, 1024, nullptr, 0);
    // bf16 conversions
    quv_prep<<<(64 * QLEN * HDIM) / 256, 256>>>(qkv_p, u, v, Qu_p, Qv_p);
    k_conv<<<(KROWS * 1024 / 4) / 256, 256>>>(qkv_p, K_p);
    vt_conv<<<dim3(KLENC / 32, 64), dim3(32, 8)>>>(qkv_p, Vt_p);
    rh_conv<<<(KLENC * 1024 / 4) / 256, 256>>>(rh_p, rhb_p);
    // BD[z] (bf16 mma), dead tiles skipped
    bd16<<<dim3(KLENC/128, QLEN/128, 64), blk, BD_SMEM>>>(Qv_p, rhb_p, BD_p, 769);
    // P(bf16) = exp(mask(AC + shift(BD)) * scale), rowsum
    ac16<<<dim3(KLENC/128, QLEN/128, 64), blk, BD_SMEM>>>(Qu_p, K_p, BD_p, S_p, rs_p);
    // ctx = (P @ V) / rsum
    pv16<<<dim3(QLEN/128, 64), blk, PV_SMEM>>>(S_p, Vt_p, rs_p, ctx_p);
    // y = ctx @ W_o
    mm_nn<<<dim3(1024/128, 4096/128), blk, NN_SMEM>>>(
        ctx_p, W_o, y_p, 4096, 1024, 1024, 1024, 1024, 1024, nullptr, 0);
    ln_kernel<<<NROWS, 256>>>(inp, y_p, ln1g, ln1b, x_p);
    // h = relu(x @ W1 + b1)
    mm_nn<<<dim3(4096/128, 4096/128), blk, NN_SMEM>>>(
        x_p, W1, h_p, 4096, 4096, 1024, 1024, 4096, 4096, b1, 1);
    // y2 = h @ W2 + b2
    mm_nn<<<dim3(1024/128, 4096/128), blk, NN_SMEM>>>(
        h_p, W2, y2_p, 4096, 1024, 4096, 4096, 1024, 1024, b2, 0);
    ln_kernel<<<NROWS, 256>>>(x_p, y2_p, ln2g, ln2b, out);
}